// round 14
// baseline (speedup 1.0000x reference)
#include <cuda_runtime.h>
#include <cuda_fp16.h>
#include <cstdint>

#define B_   4
#define S_   2048
#define H_   1024
#define NH_  16
#define HD_  64
#define MTOT (B_ * S_)          // 8192
#define HSN  (MTOT * H_)        // 8388608

#define LOG2E   1.4426950408889634f
#define QSCALE  0.1803368801111137f   // 0.125 * log2(e)

// ---------------- scratch (device globals; no allocations allowed) ----------
__device__ __half g_hsh[HSN];            // hidden states fp16 hi
__device__ __half g_hsl[HSN];            // hidden states fp16 lo (residual)
__device__ __half g_wth[3 * H_ * H_];    // W^T fp16 hi  (Wt[n*H+k] = W[k*H+n])
// Q/K/V in split-head layout [B, NH, S, HD]
// Q: hi+lo (pre-scaled by 0.125*log2e); K,V: hi only
__device__ __half g_qh[B_ * NH_ * S_ * HD_];
__device__ __half g_ql[B_ * NH_ * S_ * HD_];
__device__ __half g_kh[B_ * NH_ * S_ * HD_];
__device__ __half g_vh[B_ * NH_ * S_ * HD_];

// ---------------- helpers ---------------------------------------------------
__device__ __forceinline__ uint32_t smem_u32(const void* p) {
    uint32_t a;
    asm("{ .reg .u64 t; cvta.to.shared.u64 t, %1; cvt.u32.u64 %0, t; }"
        : "=r"(a) : "l"(p));
    return a;
}
__device__ __forceinline__ void mma16816(float* c, const uint32_t* a,
                                         uint32_t b0, uint32_t b1) {
    asm volatile(
        "mma.sync.aligned.m16n8k16.row.col.f32.f16.f16.f32 "
        "{%0,%1,%2,%3}, {%4,%5,%6,%7}, {%8,%9}, {%0,%1,%2,%3};"
        : "+f"(c[0]), "+f"(c[1]), "+f"(c[2]), "+f"(c[3])
        : "r"(a[0]), "r"(a[1]), "r"(a[2]), "r"(a[3]), "r"(b0), "r"(b1));
}
__device__ __forceinline__ void ldsm4(uint32_t* r, uint32_t addr) {
    asm volatile("ldmatrix.sync.aligned.m8n8.x4.shared.b16 {%0,%1,%2,%3}, [%4];"
                 : "=r"(r[0]), "=r"(r[1]), "=r"(r[2]), "=r"(r[3]) : "r"(addr));
}
__device__ __forceinline__ void ldsm4t(uint32_t* r, uint32_t addr) {
    asm volatile("ldmatrix.sync.aligned.m8n8.x4.trans.shared.b16 {%0,%1,%2,%3}, [%4];"
                 : "=r"(r[0]), "=r"(r[1]), "=r"(r[2]), "=r"(r[3]) : "r"(addr));
}
__device__ __forceinline__ void cp16(uint32_t dst, const void* src) {
    asm volatile("cp.async.cg.shared.global [%0], [%1], 16;"
                 :: "r"(dst), "l"(src) : "memory");
}
#define CP_COMMIT() asm volatile("cp.async.commit_group;" ::: "memory")
#define CP_WAIT1()  asm volatile("cp.async.wait_group 1;" ::: "memory")
#define CP_WAIT0()  asm volatile("cp.async.wait_group 0;" ::: "memory")

// ---------------- prep kernels ---------------------------------------------
__global__ void convert_hs_kernel(const float* __restrict__ hs) {
    const int n4 = HSN / 4;
    for (int i = blockIdx.x * blockDim.x + threadIdx.x; i < n4;
         i += gridDim.x * blockDim.x) {
        float4 v = ((const float4*)hs)[i];
        __half h0 = __float2half_rn(v.x), h1 = __float2half_rn(v.y);
        __half h2 = __float2half_rn(v.z), h3 = __float2half_rn(v.w);
        __half l0 = __float2half_rn(v.x - __half2float(h0));
        __half l1 = __float2half_rn(v.y - __half2float(h1));
        __half l2 = __float2half_rn(v.z - __half2float(h2));
        __half l3 = __float2half_rn(v.w - __half2float(h3));
        ((__half2*)g_hsh)[2 * i]     = __halves2half2(h0, h1);
        ((__half2*)g_hsh)[2 * i + 1] = __halves2half2(h2, h3);
        ((__half2*)g_hsl)[2 * i]     = __halves2half2(l0, l1);
        ((__half2*)g_hsl)[2 * i + 1] = __halves2half2(l2, l3);
    }
}

__global__ void transpose_w_kernel(const float* __restrict__ Wq,
                                   const float* __restrict__ Wk,
                                   const float* __restrict__ Wv) {
    __shared__ float tile[32][33];
    const int z = blockIdx.z;
    const float* W = (z == 0) ? Wq : (z == 1) ? Wk : Wv;
    __half* oh = g_wth + (size_t)z * H_ * H_;

    const int x = blockIdx.x * 32 + threadIdx.x;
    const int y0 = blockIdx.y * 32;
#pragma unroll
    for (int j = 0; j < 4; j++)
        tile[threadIdx.y + j * 8][threadIdx.x] =
            W[(size_t)(y0 + threadIdx.y + j * 8) * H_ + x];
    __syncthreads();
#pragma unroll
    for (int j = 0; j < 4; j++) {
        const float v = tile[threadIdx.x][threadIdx.y + j * 8];
        const int n = blockIdx.x * 32 + threadIdx.y + j * 8;
        const int k = y0 + threadIdx.x;
        oh[(size_t)n * H_ + k] = __float2half_rn(v);
    }
}

// ---------------- QKV GEMM via mma.sync, cp.async 3-stage, SW64 swizzle -----
// CTA: 128x128 tile, 256 thr / 8 warps (4x2), warp tile 32x64, BK=32.
// 2-term: (a_hi + a_lo) x b_hi.  W_lo not used at all.
#define QAB   (128 * 64)         // bytes per array per stage (8192)
#define QSTG  (3 * QAB)          // stage stride (24576): ah, al, bh
#define QSM   (3 * QSTG + 512)   // + be[128]

__global__ __launch_bounds__(256, 2) void qkv_mma_kernel(
    const float* __restrict__ bq, const float* __restrict__ bk,
    const float* __restrict__ bv,
    const float* __restrict__ qe, const float* __restrict__ ke,
    const float* __restrict__ ve,
    const int* __restrict__ idxp)
{
    extern __shared__ char smem[];
    float* be = (float*)(smem + 3 * QSTG);

    const int tid = threadIdx.x;
    const int lane = tid & 31;
    const int wid = tid >> 5;
    const int z = blockIdx.z;

    const float* bias;
    const float* emb;
    __half* ohp;
    if (z == 0)      { bias = bq; emb = qe; ohp = g_qh; }
    else if (z == 1) { bias = bk; emb = ke; ohp = g_kh; }
    else             { bias = bv; emb = ve; ohp = g_vh; }
    emb += (size_t)idxp[0] * H_;
    const float qscale = (z == 0) ? QSCALE : 1.0f;
    const bool writeLo = (z == 0);

    const int m0 = blockIdx.y * 128;
    const int n0 = blockIdx.x * 128;
    if (tid < 128) be[tid] = bias[n0 + tid] + emb[n0 + tid];

    const int wm = wid & 3;
    const int wn = wid >> 2;

    const int lrow = tid >> 1;
    const int c0 = (tid & 1) * 2;
    const int xrs = (lrow >> 1) & 3;
    const uint32_t pc0 = (uint32_t)((c0 ^ xrs) * 16);
    const uint32_t pc1 = (uint32_t)(((c0 + 1) ^ xrs) * 16);
    const size_t gA = (size_t)(m0 + lrow) * H_;
    const size_t gB = (size_t)(n0 + lrow) * H_;
    const __half* pWh = g_wth + (size_t)z * H_ * H_;

    const uint32_t sbase = smem_u32(smem);
    const uint32_t rowb = (uint32_t)(lrow * 64);

    const int arow = lane & 15;
    const int achk = lane >> 4;
    const int xrl = (arow >> 1) & 3;

    float c[2][8][4];
#pragma unroll
    for (int i = 0; i < 2; i++)
#pragma unroll
        for (int j = 0; j < 8; j++)
#pragma unroll
            for (int q = 0; q < 4; q++) c[i][j][q] = 0.f;

    auto prefetch = [&](int kt, int stg) {
        const int k0 = kt * 32;
        const uint32_t d = sbase + stg * QSTG + rowb;
        cp16(d + pc0,            g_hsh + gA + k0 + c0 * 8);
        cp16(d + pc1,            g_hsh + gA + k0 + c0 * 8 + 8);
        cp16(d + QAB + pc0,      g_hsl + gA + k0 + c0 * 8);
        cp16(d + QAB + pc1,      g_hsl + gA + k0 + c0 * 8 + 8);
        cp16(d + 2 * QAB + pc0,  pWh + gB + k0 + c0 * 8);
        cp16(d + 2 * QAB + pc1,  pWh + gB + k0 + c0 * 8 + 8);
        CP_COMMIT();
    };

    prefetch(0, 0);
    prefetch(1, 1);
    int stg = 0;
    for (int kt = 0; kt < 32; kt++) {
        if (kt < 31) CP_WAIT1(); else CP_WAIT0();
        __syncthreads();
        int pstg = stg + 2; if (pstg >= 3) pstg -= 3;
        if (kt + 2 < 32) prefetch(kt + 2, pstg);

        const uint32_t stb = sbase + stg * QSTG;
        const uint32_t aRow = stb + (wm * 32 + arow) * 64;
        const uint32_t bRow = stb + 2 * QAB + (wn * 64 + arow) * 64;

#pragma unroll
        for (int k16 = 0; k16 < 2; k16++) {
            const uint32_t cs = (uint32_t)((((achk + 2 * k16) ^ xrl)) * 16);
            uint32_t ah[2][4], al[2][4];
            ldsm4(ah[0], aRow + cs);
            ldsm4(ah[1], aRow + 1024 + cs);
            ldsm4(al[0], aRow + QAB + cs);
            ldsm4(al[1], aRow + QAB + 1024 + cs);
#pragma unroll
            for (int ng = 0; ng < 4; ng++) {
                uint32_t bh[4];
                ldsm4(bh, bRow + ng * 1024 + cs);
                mma16816(c[0][2 * ng],     ah[0], bh[0], bh[2]);
                mma16816(c[1][2 * ng],     ah[1], bh[0], bh[2]);
                mma16816(c[0][2 * ng + 1], ah[0], bh[1], bh[3]);
                mma16816(c[1][2 * ng + 1], ah[1], bh[1], bh[3]);
                mma16816(c[0][2 * ng],     al[0], bh[0], bh[2]);
                mma16816(c[1][2 * ng],     al[1], bh[0], bh[2]);
                mma16816(c[0][2 * ng + 1], al[0], bh[1], bh[3]);
                mma16816(c[1][2 * ng + 1], al[1], bh[1], bh[3]);
            }
        }
        if (++stg == 3) stg = 0;
    }

    // Epilogue: (+ bias + emb) * qscale, write fp16 hi (+ lo for Q only)
#pragma unroll
    for (int mt = 0; mt < 2; mt++) {
#pragma unroll
        for (int nt = 0; nt < 8; nt++) {
            const int mloc = wm * 32 + mt * 16 + (lane >> 2);
            const int nloc = wn * 64 + nt * 8 + (lane & 3) * 2;
            const float v00 = (c[mt][nt][0] + be[nloc])     * qscale;
            const float v01 = (c[mt][nt][1] + be[nloc + 1]) * qscale;
            const float v10 = (c[mt][nt][2] + be[nloc])     * qscale;
            const float v11 = (c[mt][nt][3] + be[nloc + 1]) * qscale;
            const int N = n0 + nloc;
            const int head = N >> 6;
            const int d = N & 63;
            const int m = m0 + mloc;
            const int bb = m >> 11;
            const int s = m & (S_ - 1);
            const size_t i0 = (((size_t)(bb * NH_ + head)) * S_ + s) * HD_ + d;
            const size_t i1 = (((size_t)(bb * NH_ + head)) * S_ + s + 8) * HD_ + d;
            __half h00 = __float2half_rn(v00), h01 = __float2half_rn(v01);
            __half h10 = __float2half_rn(v10), h11 = __float2half_rn(v11);
            *(__half2*)&ohp[i0] = __halves2half2(h00, h01);
            *(__half2*)&ohp[i1] = __halves2half2(h10, h11);
            if (writeLo) {
                *(__half2*)&g_ql[i0] = __halves2half2(
                    __float2half_rn(v00 - __half2float(h00)),
                    __float2half_rn(v01 - __half2float(h01)));
                *(__half2*)&g_ql[i1] = __halves2half2(
                    __float2half_rn(v10 - __half2float(h10)),
                    __float2half_rn(v11 - __half2float(h11)));
            }
        }
    }
}

// ---------------- flash attention via mma.sync, cp.async 3-stage ------------
// Scores: 2-term (q_hi + q_lo) x k_hi.  PV: 1-term P_hi x V_hi.
// exp2 domain (Q pre-scaled).  One __syncthreads per tile.
#define KLD   72                 // row = 144 B
#define ATB   (64 * KLD * 2)     // bytes per array per stage (9216)
#define ASTG  (2 * ATB)          // stage stride (18432): kh, vh
#define ASM   (3 * ASTG + 768)   // + msk[3][64] floats

__global__ __launch_bounds__(256, 2) void attn_mma_kernel(
    const float* __restrict__ mask,   // [B,1,1,S]
    float* __restrict__ out)          // [B,S,H]
{
    extern __shared__ char smem[];
    const uint32_t sbase = smem_u32(smem);

    const int tid = threadIdx.x;
    const int wid = tid >> 5;
    const int lane = tid & 31;
    const int bh = blockIdx.y;
    const int b = bh >> 4;
    const int h = bh & (NH_ - 1);
    const int q0 = blockIdx.x * 128 + wid * 16;

    const int r = lane >> 2;
    const int cc = (lane & 3) * 2;

    // Q fragments (hi/lo) directly from gmem in a-frag layout
    uint32_t qhf[4][4], qlf[4][4];
    {
        const __half* qb_h = g_qh + ((size_t)bh * S_ + q0) * HD_;
        const __half* qb_l = g_ql + ((size_t)bh * S_ + q0) * HD_;
#pragma unroll
        for (int dc = 0; dc < 4; dc++) {
            const int o00 = (r)     * HD_ + dc * 16 + cc;
            const int o10 = (r + 8) * HD_ + dc * 16 + cc;
            qhf[dc][0] = *(const uint32_t*)&qb_h[o00];
            qhf[dc][1] = *(const uint32_t*)&qb_h[o10];
            qhf[dc][2] = *(const uint32_t*)&qb_h[o00 + 8];
            qhf[dc][3] = *(const uint32_t*)&qb_h[o10 + 8];
            qlf[dc][0] = *(const uint32_t*)&qb_l[o00];
            qlf[dc][1] = *(const uint32_t*)&qb_l[o10];
            qlf[dc][2] = *(const uint32_t*)&qb_l[o00 + 8];
            qlf[dc][3] = *(const uint32_t*)&qb_l[o10 + 8];
        }
    }

    float o[8][4];
#pragma unroll
    for (int t = 0; t < 8; t++)
#pragma unroll
        for (int q = 0; q < 4; q++) o[t][q] = 0.f;
    float mrow0 = -1e30f, mrow1 = -1e30f;
    float lrow0 = 0.f, lrow1 = 0.f;   // per-thread partials; reduced at end

    const uint32_t lmOff = ((lane & 15) * KLD + (lane >> 4) * 8) * 2;

    const int trow = tid >> 2;
    const int tch = (tid & 3) * 2;
    const size_t kvrow = ((size_t)bh * S_ + trow) * HD_ + tch * 8;
    const uint32_t rowoff = trow * (KLD * 2) + tch * 16;
    const float* mbase = &mask[(size_t)b * S_];

    auto prefetch = [&](int kt, int stg) {
        const size_t off = kvrow + (size_t)kt * 64 * HD_;
        const uint32_t d = sbase + stg * ASTG + rowoff;
        cp16(d,            g_kh + off);
        cp16(d + 16,       g_kh + off + 8);
        cp16(d + ATB,      g_vh + off);
        cp16(d + ATB + 16, g_vh + off + 8);
        if (tid < 16)
            cp16(sbase + 3 * ASTG + stg * 256 + tid * 16,
                 mbase + kt * 64 + tid * 4);
        CP_COMMIT();
    };

    prefetch(0, 0);
    prefetch(1, 1);
    int stg = 0;
    for (int kt = 0; kt < 32; kt++) {
        if (kt < 31) CP_WAIT1(); else CP_WAIT0();
        __syncthreads();
        int pstg = stg + 2; if (pstg >= 3) pstg -= 3;
        if (kt + 2 < 32) prefetch(kt + 2, pstg);

        const uint32_t khB = sbase + stg * ASTG + lmOff;
        const uint32_t vhB = khB + ATB;
        const float* msk = (const float*)(smem + 3 * ASTG + stg * 256);

        // ---- scores: (q_hi + q_lo) x k_hi ----
        float c[8][4];
#pragma unroll
        for (int t = 0; t < 8; t++)
#pragma unroll
            for (int q = 0; q < 4; q++) c[t][q] = 0.f;

#pragma unroll
        for (int kg = 0; kg < 4; kg++) {
#pragma unroll
            for (int dc = 0; dc < 4; dc++) {
                const uint32_t off = (kg * 16 * KLD + dc * 16) * 2;
                uint32_t kf[4];
                ldsm4(kf, khB + off);
                mma16816(c[2 * kg],     qhf[dc], kf[0], kf[2]);
                mma16816(c[2 * kg + 1], qhf[dc], kf[1], kf[3]);
                mma16816(c[2 * kg],     qlf[dc], kf[0], kf[2]);
                mma16816(c[2 * kg + 1], qlf[dc], kf[1], kf[3]);
            }
        }

        // ---- softmax (base-2; deferred lsum reduction) ----
        float mx0 = mrow0, mx1 = mrow1;
#pragma unroll
        for (int t = 0; t < 8; t++) {
            const float mk0 = msk[8 * t + cc];
            const float mk1 = msk[8 * t + cc + 1];
            c[t][0] = fmaf(mk0, LOG2E, c[t][0]);
            c[t][1] = fmaf(mk1, LOG2E, c[t][1]);
            c[t][2] = fmaf(mk0, LOG2E, c[t][2]);
            c[t][3] = fmaf(mk1, LOG2E, c[t][3]);
            mx0 = fmaxf(mx0, fmaxf(c[t][0], c[t][1]));
            mx1 = fmaxf(mx1, fmaxf(c[t][2], c[t][3]));
        }
        mx0 = fmaxf(mx0, __shfl_xor_sync(0xffffffffu, mx0, 1));
        mx0 = fmaxf(mx0, __shfl_xor_sync(0xffffffffu, mx0, 2));
        mx1 = fmaxf(mx1, __shfl_xor_sync(0xffffffffu, mx1, 1));
        mx1 = fmaxf(mx1, __shfl_xor_sync(0xffffffffu, mx1, 2));

        if (mx0 > mrow0 || mx1 > mrow1) {      // sc != 1 → rescale (rare)
            const float sc0 = exp2f(mrow0 - mx0);
            const float sc1 = exp2f(mrow1 - mx1);
            lrow0 *= sc0; lrow1 *= sc1;
#pragma unroll
            for (int t = 0; t < 8; t++) {
                o[t][0] *= sc0; o[t][1] *= sc0;
                o[t][2] *= sc1; o[t][3] *= sc1;
            }
            mrow0 = mx0; mrow1 = mx1;
        }
#pragma unroll
        for (int t = 0; t < 8; t++) {
            c[t][0] = exp2f(c[t][0] - mrow0);
            c[t][1] = exp2f(c[t][1] - mrow0);
            c[t][2] = exp2f(c[t][2] - mrow1);
            c[t][3] = exp2f(c[t][3] - mrow1);
            lrow0 += c[t][0] + c[t][1];
            lrow1 += c[t][2] + c[t][3];
        }

        // ---- PV (1-term: P_hi x V_hi) ----
#pragma unroll
        for (int kg = 0; kg < 4; kg++) {
            uint32_t aph[4];
            {
                __half2 t0 = __floats2half2_rn(c[2 * kg][0], c[2 * kg][1]);
                __half2 t1 = __floats2half2_rn(c[2 * kg][2], c[2 * kg][3]);
                __half2 t2 = __floats2half2_rn(c[2 * kg + 1][0], c[2 * kg + 1][1]);
                __half2 t3 = __floats2half2_rn(c[2 * kg + 1][2], c[2 * kg + 1][3]);
                aph[0] = *(uint32_t*)&t0;
                aph[1] = *(uint32_t*)&t1;
                aph[2] = *(uint32_t*)&t2;
                aph[3] = *(uint32_t*)&t3;
            }
#pragma unroll
            for (int hc = 0; hc < 4; hc++) {
                const uint32_t off = (kg * 16 * KLD + hc * 16) * 2;
                uint32_t vf[4];
                ldsm4t(vf, vhB + off);
                mma16816(o[2 * hc],     aph, vf[0], vf[1]);
                mma16816(o[2 * hc + 1], aph, vf[2], vf[3]);
            }
        }
        if (++stg == 3) stg = 0;
    }

    // ---- final lsum reduction + normalize + write ----
    lrow0 += __shfl_xor_sync(0xffffffffu, lrow0, 1);
    lrow0 += __shfl_xor_sync(0xffffffffu, lrow0, 2);
    lrow1 += __shfl_xor_sync(0xffffffffu, lrow1, 1);
    lrow1 += __shfl_xor_sync(0xffffffffu, lrow1, 2);
    const float inv0 = 1.0f / lrow0;
    const float inv1 = 1.0f / lrow1;
    const int srow = q0 + r;
    float* ob0 = out + ((size_t)b * S_ + srow) * H_ + h * HD_;
    float* ob1 = out + ((size_t)b * S_ + srow + 8) * H_ + h * HD_;
#pragma unroll
    for (int t = 0; t < 8; t++) {
        float2 w0, w1;
        w0.x = o[t][0] * inv0; w0.y = o[t][1] * inv0;
        w1.x = o[t][2] * inv1; w1.y = o[t][3] * inv1;
        *(float2*)&ob0[8 * t + cc] = w0;
        *(float2*)&ob1[8 * t + cc] = w1;
    }
}

// ---------------------------------------------------------------------------
extern "C" void kernel_launch(void* const* d_in, const int* in_sizes, int n_in,
                              void* d_out, int out_size)
{
    const float* hs   = (const float*)d_in[0];
    const float* mask = (const float*)d_in[1];
    const float* Wq   = (const float*)d_in[2];
    const float* bq   = (const float*)d_in[3];
    const float* Wk   = (const float*)d_in[4];
    const float* bk   = (const float*)d_in[5];
    const float* Wv   = (const float*)d_in[6];
    const float* bv   = (const float*)d_in[7];
    const float* qe   = (const float*)d_in[8];
    const float* ke   = (const float*)d_in[9];
    const float* ve   = (const float*)d_in[10];
    const int*   idx  = (const int*)d_in[11];
    float* out = (float*)d_out;

    static bool attr_done = false;
    if (!attr_done) {
        cudaFuncSetAttribute(qkv_mma_kernel,
                             cudaFuncAttributeMaxDynamicSharedMemorySize, QSM);
        cudaFuncSetAttribute(attn_mma_kernel,
                             cudaFuncAttributeMaxDynamicSharedMemorySize, ASM);
        attr_done = true;
    }

    convert_hs_kernel<<<2048, 256>>>(hs);
    transpose_w_kernel<<<dim3(32, 32, 3), dim3(32, 8)>>>(Wq, Wk, Wv);
    qkv_mma_kernel<<<dim3(8, 64, 3), 256, QSM>>>(bq, bk, bv, qe, ke, ve, idx);
    attn_mma_kernel<<<dim3(16, 64), 256, ASM>>>(mask, out);
}

// round 16
// speedup vs baseline: 1.0655x; 1.0655x over previous
#include <cuda_runtime.h>
#include <cuda_fp16.h>
#include <cstdint>

#define B_   4
#define S_   2048
#define H_   1024
#define NH_  16
#define HD_  64
#define MTOT (B_ * S_)          // 8192
#define HSN  (MTOT * H_)        // 8388608

#define LOG2E   1.4426950408889634f
#define QSCALE  0.1803368801111137f   // 0.125 * log2(e)

// ---------------- scratch (device globals; no allocations allowed) ----------
__device__ __half g_hsh[HSN];            // hidden states fp16 hi
__device__ __half g_hsl[HSN];            // hidden states fp16 lo (residual)
__device__ __half g_wth[3 * H_ * H_];    // W^T fp16 hi  (Wt[n*H+k] = W[k*H+n])
// Q/K/V in split-head layout [B, NH, S, HD]
// Q: hi+lo (pre-scaled by 0.125*log2e); K,V: hi only
__device__ __half g_qh[B_ * NH_ * S_ * HD_];
__device__ __half g_ql[B_ * NH_ * S_ * HD_];
__device__ __half g_kh[B_ * NH_ * S_ * HD_];
__device__ __half g_vh[B_ * NH_ * S_ * HD_];

// ---------------- helpers ---------------------------------------------------
__device__ __forceinline__ uint32_t smem_u32(const void* p) {
    uint32_t a;
    asm("{ .reg .u64 t; cvta.to.shared.u64 t, %1; cvt.u32.u64 %0, t; }"
        : "=r"(a) : "l"(p));
    return a;
}
__device__ __forceinline__ float ex2(float x) {
    float y;
    asm("ex2.approx.f32 %0, %1;" : "=f"(y) : "f"(x));
    return y;
}
__device__ __forceinline__ void mma16816(float* c, const uint32_t* a,
                                         uint32_t b0, uint32_t b1) {
    asm volatile(
        "mma.sync.aligned.m16n8k16.row.col.f32.f16.f16.f32 "
        "{%0,%1,%2,%3}, {%4,%5,%6,%7}, {%8,%9}, {%0,%1,%2,%3};"
        : "+f"(c[0]), "+f"(c[1]), "+f"(c[2]), "+f"(c[3])
        : "r"(a[0]), "r"(a[1]), "r"(a[2]), "r"(a[3]), "r"(b0), "r"(b1));
}
__device__ __forceinline__ void ldsm4(uint32_t* r, uint32_t addr) {
    asm volatile("ldmatrix.sync.aligned.m8n8.x4.shared.b16 {%0,%1,%2,%3}, [%4];"
                 : "=r"(r[0]), "=r"(r[1]), "=r"(r[2]), "=r"(r[3]) : "r"(addr));
}
__device__ __forceinline__ void ldsm4t(uint32_t* r, uint32_t addr) {
    asm volatile("ldmatrix.sync.aligned.m8n8.x4.trans.shared.b16 {%0,%1,%2,%3}, [%4];"
                 : "=r"(r[0]), "=r"(r[1]), "=r"(r[2]), "=r"(r[3]) : "r"(addr));
}
__device__ __forceinline__ void cp16(uint32_t dst, const void* src) {
    asm volatile("cp.async.cg.shared.global [%0], [%1], 16;"
                 :: "r"(dst), "l"(src) : "memory");
}
#define CP_COMMIT() asm volatile("cp.async.commit_group;" ::: "memory")
#define CP_WAIT1()  asm volatile("cp.async.wait_group 1;" ::: "memory")
#define CP_WAIT0()  asm volatile("cp.async.wait_group 0;" ::: "memory")

// ---------------- prep kernels ---------------------------------------------
__global__ void convert_hs_kernel(const float* __restrict__ hs) {
    const int n4 = HSN / 4;
    for (int i = blockIdx.x * blockDim.x + threadIdx.x; i < n4;
         i += gridDim.x * blockDim.x) {
        float4 v = ((const float4*)hs)[i];
        __half h0 = __float2half_rn(v.x), h1 = __float2half_rn(v.y);
        __half h2 = __float2half_rn(v.z), h3 = __float2half_rn(v.w);
        __half l0 = __float2half_rn(v.x - __half2float(h0));
        __half l1 = __float2half_rn(v.y - __half2float(h1));
        __half l2 = __float2half_rn(v.z - __half2float(h2));
        __half l3 = __float2half_rn(v.w - __half2float(h3));
        ((__half2*)g_hsh)[2 * i]     = __halves2half2(h0, h1);
        ((__half2*)g_hsh)[2 * i + 1] = __halves2half2(h2, h3);
        ((__half2*)g_hsl)[2 * i]     = __halves2half2(l0, l1);
        ((__half2*)g_hsl)[2 * i + 1] = __halves2half2(l2, l3);
    }
}

__global__ void transpose_w_kernel(const float* __restrict__ Wq,
                                   const float* __restrict__ Wk,
                                   const float* __restrict__ Wv) {
    __shared__ float tile[32][33];
    const int z = blockIdx.z;
    const float* W = (z == 0) ? Wq : (z == 1) ? Wk : Wv;
    __half* oh = g_wth + (size_t)z * H_ * H_;

    const int x = blockIdx.x * 32 + threadIdx.x;
    const int y0 = blockIdx.y * 32;
#pragma unroll
    for (int j = 0; j < 4; j++)
        tile[threadIdx.y + j * 8][threadIdx.x] =
            W[(size_t)(y0 + threadIdx.y + j * 8) * H_ + x];
    __syncthreads();
#pragma unroll
    for (int j = 0; j < 4; j++) {
        const float v = tile[threadIdx.x][threadIdx.y + j * 8];
        const int n = blockIdx.x * 32 + threadIdx.y + j * 8;
        const int k = y0 + threadIdx.x;
        oh[(size_t)n * H_ + k] = __float2half_rn(v);
    }
}

// ---------------- QKV GEMM via mma.sync, cp.async 3-stage, SW64 swizzle -----
// CTA: 128x128 tile, 256 thr / 8 warps (4x2), warp tile 32x64, BK=32.
// Q (z=0): 2-term (a_hi + a_lo) x b_hi.  K,V (z>0): 1-term a_hi x b_hi.
#define QAB   (128 * 64)         // bytes per array per stage (8192)
#define QSTG  (3 * QAB)          // stage stride (24576): ah, al, bh
#define QSM   (3 * QSTG + 512)   // + be[128]

__global__ __launch_bounds__(256, 2) void qkv_mma_kernel(
    const float* __restrict__ bq, const float* __restrict__ bk,
    const float* __restrict__ bv,
    const float* __restrict__ qe, const float* __restrict__ ke,
    const float* __restrict__ ve,
    const int* __restrict__ idxp)
{
    extern __shared__ char smem[];
    float* be = (float*)(smem + 3 * QSTG);

    const int tid = threadIdx.x;
    const int lane = tid & 31;
    const int wid = tid >> 5;
    const int z = blockIdx.z;

    const float* bias;
    const float* emb;
    __half* ohp;
    if (z == 0)      { bias = bq; emb = qe; ohp = g_qh; }
    else if (z == 1) { bias = bk; emb = ke; ohp = g_kh; }
    else             { bias = bv; emb = ve; ohp = g_vh; }
    emb += (size_t)idxp[0] * H_;
    const float qscale = (z == 0) ? QSCALE : 1.0f;
    const bool twoTerm = (z == 0);

    const int m0 = blockIdx.y * 128;
    const int n0 = blockIdx.x * 128;
    if (tid < 128) be[tid] = bias[n0 + tid] + emb[n0 + tid];

    const int wm = wid & 3;
    const int wn = wid >> 2;

    const int lrow = tid >> 1;
    const int c0 = (tid & 1) * 2;
    const int xrs = (lrow >> 1) & 3;
    const uint32_t pc0 = (uint32_t)((c0 ^ xrs) * 16);
    const uint32_t pc1 = (uint32_t)(((c0 + 1) ^ xrs) * 16);
    const size_t gA = (size_t)(m0 + lrow) * H_;
    const size_t gB = (size_t)(n0 + lrow) * H_;
    const __half* pWh = g_wth + (size_t)z * H_ * H_;

    const uint32_t sbase = smem_u32(smem);
    const uint32_t rowb = (uint32_t)(lrow * 64);

    const int arow = lane & 15;
    const int achk = lane >> 4;
    const int xrl = (arow >> 1) & 3;

    float c[2][8][4];
#pragma unroll
    for (int i = 0; i < 2; i++)
#pragma unroll
        for (int j = 0; j < 8; j++)
#pragma unroll
            for (int q = 0; q < 4; q++) c[i][j][q] = 0.f;

    auto prefetch = [&](int kt, int stg) {
        const int k0 = kt * 32;
        const uint32_t d = sbase + stg * QSTG + rowb;
        cp16(d + pc0,            g_hsh + gA + k0 + c0 * 8);
        cp16(d + pc1,            g_hsh + gA + k0 + c0 * 8 + 8);
        if (twoTerm) {
            cp16(d + QAB + pc0,  g_hsl + gA + k0 + c0 * 8);
            cp16(d + QAB + pc1,  g_hsl + gA + k0 + c0 * 8 + 8);
        }
        cp16(d + 2 * QAB + pc0,  pWh + gB + k0 + c0 * 8);
        cp16(d + 2 * QAB + pc1,  pWh + gB + k0 + c0 * 8 + 8);
        CP_COMMIT();
    };

    prefetch(0, 0);
    prefetch(1, 1);
    int stg = 0;
    for (int kt = 0; kt < 32; kt++) {
        if (kt < 31) CP_WAIT1(); else CP_WAIT0();
        __syncthreads();
        int pstg = stg + 2; if (pstg >= 3) pstg -= 3;
        if (kt + 2 < 32) prefetch(kt + 2, pstg);

        const uint32_t stb = sbase + stg * QSTG;
        const uint32_t aRow = stb + (wm * 32 + arow) * 64;
        const uint32_t bRow = stb + 2 * QAB + (wn * 64 + arow) * 64;

#pragma unroll
        for (int k16 = 0; k16 < 2; k16++) {
            const uint32_t cs = (uint32_t)((((achk + 2 * k16) ^ xrl)) * 16);
            uint32_t ah[2][4];
            ldsm4(ah[0], aRow + cs);
            ldsm4(ah[1], aRow + 1024 + cs);
            uint32_t al[2][4];
            if (twoTerm) {
                ldsm4(al[0], aRow + QAB + cs);
                ldsm4(al[1], aRow + QAB + 1024 + cs);
            }
#pragma unroll
            for (int ng = 0; ng < 4; ng++) {
                uint32_t bh[4];
                ldsm4(bh, bRow + ng * 1024 + cs);
                mma16816(c[0][2 * ng],     ah[0], bh[0], bh[2]);
                mma16816(c[1][2 * ng],     ah[1], bh[0], bh[2]);
                mma16816(c[0][2 * ng + 1], ah[0], bh[1], bh[3]);
                mma16816(c[1][2 * ng + 1], ah[1], bh[1], bh[3]);
                if (twoTerm) {
                    mma16816(c[0][2 * ng],     al[0], bh[0], bh[2]);
                    mma16816(c[1][2 * ng],     al[1], bh[0], bh[2]);
                    mma16816(c[0][2 * ng + 1], al[0], bh[1], bh[3]);
                    mma16816(c[1][2 * ng + 1], al[1], bh[1], bh[3]);
                }
            }
        }
        if (++stg == 3) stg = 0;
    }

    // Epilogue: (+ bias + emb) * qscale, write fp16 hi (+ lo for Q only)
#pragma unroll
    for (int mt = 0; mt < 2; mt++) {
#pragma unroll
        for (int nt = 0; nt < 8; nt++) {
            const int mloc = wm * 32 + mt * 16 + (lane >> 2);
            const int nloc = wn * 64 + nt * 8 + (lane & 3) * 2;
            const float v00 = (c[mt][nt][0] + be[nloc])     * qscale;
            const float v01 = (c[mt][nt][1] + be[nloc + 1]) * qscale;
            const float v10 = (c[mt][nt][2] + be[nloc])     * qscale;
            const float v11 = (c[mt][nt][3] + be[nloc + 1]) * qscale;
            const int N = n0 + nloc;
            const int head = N >> 6;
            const int d = N & 63;
            const int m = m0 + mloc;
            const int bb = m >> 11;
            const int s = m & (S_ - 1);
            const size_t i0 = (((size_t)(bb * NH_ + head)) * S_ + s) * HD_ + d;
            const size_t i1 = (((size_t)(bb * NH_ + head)) * S_ + s + 8) * HD_ + d;
            __half h00 = __float2half_rn(v00), h01 = __float2half_rn(v01);
            __half h10 = __float2half_rn(v10), h11 = __float2half_rn(v11);
            *(__half2*)&ohp[i0] = __halves2half2(h00, h01);
            *(__half2*)&ohp[i1] = __halves2half2(h10, h11);
            if (twoTerm) {
                *(__half2*)&g_ql[i0] = __halves2half2(
                    __float2half_rn(v00 - __half2float(h00)),
                    __float2half_rn(v01 - __half2float(h01)));
                *(__half2*)&g_ql[i1] = __halves2half2(
                    __float2half_rn(v10 - __half2float(h10)),
                    __float2half_rn(v11 - __half2float(h11)));
            }
        }
    }
}

// ---------------- flash attention via mma.sync, cp.async 2-stage ------------
// Scores: 2-term (q_hi + q_lo) x k_hi.  PV: 1-term P_hi x V_hi.
// exp2 domain (Q pre-scaled); ex2.approx MUFU.
#define KLD   72                 // row = 144 B
#define ATB   (64 * KLD * 2)     // bytes per array per stage (9216)
#define ASTG  (2 * ATB)          // stage stride (18432): kh, vh
#define ASM   (2 * ASTG + 512)   // + msk[2][64] floats

__global__ __launch_bounds__(256, 2) void attn_mma_kernel(
    const float* __restrict__ mask,   // [B,1,1,S]
    float* __restrict__ out)          // [B,S,H]
{
    extern __shared__ char smem[];
    const uint32_t sbase = smem_u32(smem);

    const int tid = threadIdx.x;
    const int wid = tid >> 5;
    const int lane = tid & 31;
    const int bh = blockIdx.y;
    const int b = bh >> 4;
    const int h = bh & (NH_ - 1);
    const int q0 = blockIdx.x * 128 + wid * 16;

    const int r = lane >> 2;
    const int cc = (lane & 3) * 2;

    // Q fragments (hi/lo) directly from gmem in a-frag layout
    uint32_t qhf[4][4], qlf[4][4];
    {
        const __half* qb_h = g_qh + ((size_t)bh * S_ + q0) * HD_;
        const __half* qb_l = g_ql + ((size_t)bh * S_ + q0) * HD_;
#pragma unroll
        for (int dc = 0; dc < 4; dc++) {
            const int o00 = (r)     * HD_ + dc * 16 + cc;
            const int o10 = (r + 8) * HD_ + dc * 16 + cc;
            qhf[dc][0] = *(const uint32_t*)&qb_h[o00];
            qhf[dc][1] = *(const uint32_t*)&qb_h[o10];
            qhf[dc][2] = *(const uint32_t*)&qb_h[o00 + 8];
            qhf[dc][3] = *(const uint32_t*)&qb_h[o10 + 8];
            qlf[dc][0] = *(const uint32_t*)&qb_l[o00];
            qlf[dc][1] = *(const uint32_t*)&qb_l[o10];
            qlf[dc][2] = *(const uint32_t*)&qb_l[o00 + 8];
            qlf[dc][3] = *(const uint32_t*)&qb_l[o10 + 8];
        }
    }

    float o[8][4];
#pragma unroll
    for (int t = 0; t < 8; t++)
#pragma unroll
        for (int q = 0; q < 4; q++) o[t][q] = 0.f;
    float mrow0 = -1e30f, mrow1 = -1e30f;
    float lrow0 = 0.f, lrow1 = 0.f;   // per-thread partials; reduced at end

    const uint32_t lmOff = ((lane & 15) * KLD + (lane >> 4) * 8) * 2;

    const int trow = tid >> 2;
    const int tch = (tid & 3) * 2;
    const size_t kvrow = ((size_t)bh * S_ + trow) * HD_ + tch * 8;
    const uint32_t rowoff = trow * (KLD * 2) + tch * 16;
    const float* mbase = &mask[(size_t)b * S_];

    auto prefetch = [&](int kt, int stg) {
        const size_t off = kvrow + (size_t)kt * 64 * HD_;
        const uint32_t d = sbase + stg * ASTG + rowoff;
        cp16(d,            g_kh + off);
        cp16(d + 16,       g_kh + off + 8);
        cp16(d + ATB,      g_vh + off);
        cp16(d + ATB + 16, g_vh + off + 8);
        if (tid < 16)
            cp16(sbase + 2 * ASTG + stg * 256 + tid * 16,
                 mbase + kt * 64 + tid * 4);
        CP_COMMIT();
    };

    prefetch(0, 0);
    for (int kt = 0; kt < 32; kt++) {
        const int stg = kt & 1;
        if (kt + 1 < 32) { prefetch(kt + 1, stg ^ 1); CP_WAIT1(); }
        else             { CP_WAIT0(); }
        __syncthreads();

        const uint32_t khB = sbase + stg * ASTG + lmOff;
        const uint32_t vhB = khB + ATB;
        const float* msk = (const float*)(smem + 2 * ASTG + stg * 256);

        // ---- scores: (q_hi + q_lo) x k_hi ----
        float c[8][4];
#pragma unroll
        for (int t = 0; t < 8; t++)
#pragma unroll
            for (int q = 0; q < 4; q++) c[t][q] = 0.f;

#pragma unroll
        for (int kg = 0; kg < 4; kg++) {
#pragma unroll
            for (int dc = 0; dc < 4; dc++) {
                const uint32_t off = (kg * 16 * KLD + dc * 16) * 2;
                uint32_t kf[4];
                ldsm4(kf, khB + off);
                mma16816(c[2 * kg],     qhf[dc], kf[0], kf[2]);
                mma16816(c[2 * kg + 1], qhf[dc], kf[1], kf[3]);
                mma16816(c[2 * kg],     qlf[dc], kf[0], kf[2]);
                mma16816(c[2 * kg + 1], qlf[dc], kf[1], kf[3]);
            }
        }

        // ---- softmax (base-2; deferred lsum reduction; ex2.approx) ----
        float mx0 = mrow0, mx1 = mrow1;
#pragma unroll
        for (int t = 0; t < 8; t++) {
            const float mk0 = msk[8 * t + cc];
            const float mk1 = msk[8 * t + cc + 1];
            c[t][0] = fmaf(mk0, LOG2E, c[t][0]);
            c[t][1] = fmaf(mk1, LOG2E, c[t][1]);
            c[t][2] = fmaf(mk0, LOG2E, c[t][2]);
            c[t][3] = fmaf(mk1, LOG2E, c[t][3]);
            mx0 = fmaxf(mx0, fmaxf(c[t][0], c[t][1]));
            mx1 = fmaxf(mx1, fmaxf(c[t][2], c[t][3]));
        }
        mx0 = fmaxf(mx0, __shfl_xor_sync(0xffffffffu, mx0, 1));
        mx0 = fmaxf(mx0, __shfl_xor_sync(0xffffffffu, mx0, 2));
        mx1 = fmaxf(mx1, __shfl_xor_sync(0xffffffffu, mx1, 1));
        mx1 = fmaxf(mx1, __shfl_xor_sync(0xffffffffu, mx1, 2));

        if (mx0 > mrow0 || mx1 > mrow1) {      // sc != 1 → rescale (rare)
            const float sc0 = ex2(mrow0 - mx0);
            const float sc1 = ex2(mrow1 - mx1);
            lrow0 *= sc0; lrow1 *= sc1;
#pragma unroll
            for (int t = 0; t < 8; t++) {
                o[t][0] *= sc0; o[t][1] *= sc0;
                o[t][2] *= sc1; o[t][3] *= sc1;
            }
            mrow0 = mx0; mrow1 = mx1;
        }
#pragma unroll
        for (int t = 0; t < 8; t++) {
            c[t][0] = ex2(c[t][0] - mrow0);
            c[t][1] = ex2(c[t][1] - mrow0);
            c[t][2] = ex2(c[t][2] - mrow1);
            c[t][3] = ex2(c[t][3] - mrow1);
            lrow0 += c[t][0] + c[t][1];
            lrow1 += c[t][2] + c[t][3];
        }

        // ---- PV (1-term: P_hi x V_hi) ----
#pragma unroll
        for (int kg = 0; kg < 4; kg++) {
            uint32_t aph[4];
            {
                __half2 t0 = __floats2half2_rn(c[2 * kg][0], c[2 * kg][1]);
                __half2 t1 = __floats2half2_rn(c[2 * kg][2], c[2 * kg][3]);
                __half2 t2 = __floats2half2_rn(c[2 * kg + 1][0], c[2 * kg + 1][1]);
                __half2 t3 = __floats2half2_rn(c[2 * kg + 1][2], c[2 * kg + 1][3]);
                aph[0] = *(uint32_t*)&t0;
                aph[1] = *(uint32_t*)&t1;
                aph[2] = *(uint32_t*)&t2;
                aph[3] = *(uint32_t*)&t3;
            }
#pragma unroll
            for (int hc = 0; hc < 4; hc++) {
                const uint32_t off = (kg * 16 * KLD + hc * 16) * 2;
                uint32_t vf[4];
                ldsm4t(vf, vhB + off);
                mma16816(o[2 * hc],     aph, vf[0], vf[1]);
                mma16816(o[2 * hc + 1], aph, vf[2], vf[3]);
            }
        }
        __syncthreads();
    }

    // ---- final lsum reduction + normalize + write ----
    lrow0 += __shfl_xor_sync(0xffffffffu, lrow0, 1);
    lrow0 += __shfl_xor_sync(0xffffffffu, lrow0, 2);
    lrow1 += __shfl_xor_sync(0xffffffffu, lrow1, 1);
    lrow1 += __shfl_xor_sync(0xffffffffu, lrow1, 2);
    const float inv0 = 1.0f / lrow0;
    const float inv1 = 1.0f / lrow1;
    const int srow = q0 + r;
    float* ob0 = out + ((size_t)b * S_ + srow) * H_ + h * HD_;
    float* ob1 = out + ((size_t)b * S_ + srow + 8) * H_ + h * HD_;
#pragma unroll
    for (int t = 0; t < 8; t++) {
        float2 w0, w1;
        w0.x = o[t][0] * inv0; w0.y = o[t][1] * inv0;
        w1.x = o[t][2] * inv1; w1.y = o[t][3] * inv1;
        *(float2*)&ob0[8 * t + cc] = w0;
        *(float2*)&ob1[8 * t + cc] = w1;
    }
}

// ---------------------------------------------------------------------------
extern "C" void kernel_launch(void* const* d_in, const int* in_sizes, int n_in,
                              void* d_out, int out_size)
{
    const float* hs   = (const float*)d_in[0];
    const float* mask = (const float*)d_in[1];
    const float* Wq   = (const float*)d_in[2];
    const float* bq   = (const float*)d_in[3];
    const float* Wk   = (const float*)d_in[4];
    const float* bk   = (const float*)d_in[5];
    const float* Wv   = (const float*)d_in[6];
    const float* bv   = (const float*)d_in[7];
    const float* qe   = (const float*)d_in[8];
    const float* ke   = (const float*)d_in[9];
    const float* ve   = (const float*)d_in[10];
    const int*   idx  = (const int*)d_in[11];
    float* out = (float*)d_out;

    static bool attr_done = false;
    if (!attr_done) {
        cudaFuncSetAttribute(qkv_mma_kernel,
                             cudaFuncAttributeMaxDynamicSharedMemorySize, QSM);
        cudaFuncSetAttribute(attn_mma_kernel,
                             cudaFuncAttributeMaxDynamicSharedMemorySize, ASM);
        attr_done = true;
    }

    convert_hs_kernel<<<2048, 256>>>(hs);
    transpose_w_kernel<<<dim3(32, 32, 3), dim3(32, 8)>>>(Wq, Wk, Wv);
    qkv_mma_kernel<<<dim3(8, 64, 3), 256, QSM>>>(bq, bk, bv, qe, ke, ve, idx);
    attn_mma_kernel<<<dim3(16, 64), 256, ASM>>>(mask, out);
}